// round 15
// baseline (speedup 1.0000x reference)
#include <cuda_runtime.h>
#include <math.h>
#include <stdint.h>

// ---------------- problem constants ----------------
#define NN     200000
#define NEDGE  800000
#define CBB    480
#define CT     484
#define FDIM   128
#define NPIX   (FDIM*FDIM)
#define HID    128
#define KIN    488
#define NCELL  (FDIM*FDIM)

// ---------------- smem layout (bytes) ----------------
#define A1_STR   144                   // 36 floats -> scalar A-frag LDS conflict-free
#define B1_STR   160                   // 40 floats -> LDS.64 B-frag conflict-free
#define A1_OFF(b) ((b)*18432)          // 2 x 128x144
#define B1_OFF(b) (36864 + (b)*20480)  // 2 x 128x160, ends 77824
#define A2_OFF   0                     // h1 tile (GEMM2 phase), overlaps A1/B1
#define A2_STR   528                   // 132 floats
#define B2_OFF   77824                 // 128x160 single buffer
#define B2_STR   160
#define PQ_OFF   98304                 // int4[128]
#define WQ_OFF   100352                // float4[128]
#define SQ_OFF   102400                // float4[128]
#define ND_OFF   104448                // int[128] permuted node ids
#define SMEM_BYTES 104960              // x2 CTAs = 209920 < 228KB

// ---------------- device scratch ----------------
__device__ float g_ft[(size_t)NPIX * CT + 32];  // (pixel, channel) fp32 feature map
__device__ float g_W1t[128*512];                // [n][k'] tf32, permuted cols + pair-permute
__device__ float g_W2t[128*128];                // [n][k] tf32, pair-permute
__device__ int g_deg[NN];
__device__ int g_perm[NN];                      // nodes sorted by pixel cell
__device__ int g_bcnt[NCELL];
__device__ int g_boff[NCELL];
__device__ int g_maxdeg;
__device__ int g_e64;

// pair-permute within each 8: col j -> pos 2*(j%4) + j/4  => (j, j+4) adjacent
__device__ __forceinline__ int permpos(int r) {
    return (r & ~7) + ((r & 3) << 1) + ((r >> 2) & 1);
}

// ---------------- helpers ----------------
__device__ __forceinline__ void cp16(void* s, const void* g) {
    unsigned ss = (unsigned)__cvta_generic_to_shared(s);
    asm volatile("cp.async.cg.shared.global [%0], [%1], 16;" :: "r"(ss), "l"(g));
}
#define CP_COMMIT() asm volatile("cp.async.commit_group;")
#define CP_WAIT0()  asm volatile("cp.async.wait_group 0;" ::: "memory")

__device__ __forceinline__ uint32_t to_tf32(float v) {
    uint32_t r;
    asm("cvt.rna.tf32.f32 %0, %1;" : "=r"(r) : "f"(v));
    return r;
}
__device__ __forceinline__ void mma_tf32(float* d, const uint32_t* a, uint32_t b0, uint32_t b1) {
    asm("mma.sync.aligned.m16n8k8.row.col.f32.tf32.tf32.f32 "
        "{%0,%1,%2,%3}, {%4,%5,%6,%7}, {%8,%9}, {%0,%1,%2,%3};"
        : "+f"(d[0]), "+f"(d[1]), "+f"(d[2]), "+f"(d[3])
        : "r"(a[0]), "r"(a[1]), "r"(a[2]), "r"(a[3]), "r"(b0), "r"(b1));
}
// A fragment m16k8: a0=(row,col) a1=(row+8,col) a2=(row,col+4) a3=(row+8,col+4)
__device__ __forceinline__ void ldA(uint32_t* a, const char* A, int row, int col, int str) {
    const char* p = A + row * str + col * 4;
    a[0] = *(const uint32_t*)p;
    a[1] = *(const uint32_t*)(p + 8 * str);
    a[2] = *(const uint32_t*)(p + 16);
    a[3] = *(const uint32_t*)(p + 8 * str + 16);
}

// builder: one m, one k-quad (k0..k0+3)
__device__ __forceinline__ void bld_issue4(const int4* __restrict__ Pq, int m, int k0, float4* f) {
    if (k0 < CT) {
        int4 q = Pq[m];
        const float* __restrict__ ft = g_ft;
        f[0] = *(const float4*)(ft + q.x + k0);
        f[1] = *(const float4*)(ft + q.y + k0);
        f[2] = *(const float4*)(ft + q.z + k0);
        f[3] = *(const float4*)(ft + q.w + k0);
    }
}
__device__ __forceinline__ void bld_store4(const float4* __restrict__ Wq, const float4* __restrict__ Sq,
        int m, int k0, const float4* f, char* dst) {
    float4 v;
    if (k0 < CT) {
        float4 w = Wq[m];
        v.x = w.x * f[0].x + w.y * f[1].x + w.z * f[2].x + w.w * f[3].x;
        v.y = w.x * f[0].y + w.y * f[1].y + w.z * f[2].y + w.w * f[3].y;
        v.z = w.x * f[0].z + w.y * f[1].z + w.z * f[2].z + w.w * f[3].z;
        v.w = w.x * f[0].w + w.y * f[1].w + w.z * f[2].w + w.w * f[3].w;
    } else if (k0 == 484) {
        v = Sq[m];                      // k 484..487 = coordx, coordy, deg, dist
    } else {
        v = make_float4(0.f, 0.f, 0.f, 0.f);
    }
    uint4 t = make_uint4(to_tf32(v.x), to_tf32(v.y), to_tf32(v.z), to_tf32(v.w));
    *(uint4*)dst = t;
}

__device__ __forceinline__ void b1fill(int c, char* dst, int tid) {
    #pragma unroll
    for (int i = 0; i < 4; i++) {
        int id = tid * 4 + i;            // 1024 granules of 16B
        int r = id >> 3, g8 = id & 7;
        cp16(dst + r * B1_STR + g8 * 16, (const char*)g_W1t + r * 2048 + c * 128 + g8 * 16);
    }
}
__device__ __forceinline__ void b2fill(int c, char* dst, int tid) {
    #pragma unroll
    for (int i = 0; i < 4; i++) {
        int id = tid * 4 + i;
        int r = id >> 3, g8 = id & 7;
        cp16(dst + r * B2_STR + g8 * 16, (const char*)g_W2t + r * 512 + c * 128 + g8 * 16);
    }
}

// cell index, identical clamping to the main kernel
__device__ __forceinline__ int cell_of(float vx, float vy) {
    int x0 = min(max((int)floorf(vx * (127.0f / 512.0f)), 0), FDIM - 1);
    int y0 = min(max((int)floorf(vy * (127.0f / 512.0f)), 0), FDIM - 1);
    return y0 * FDIM + x0;
}

// ---------------- prep kernels ----------------
#define PB_Z   782
#define PB_W1  (PB_Z + 128)
#define PB_W2  (PB_W1 + 64)
#define PB_T   (PB_W2 + 8192)

__global__ void k_prep(const int* __restrict__ e,
                       const float* __restrict__ W1, const float* __restrict__ W2,
                       const float* __restrict__ bb, const float* __restrict__ seg) {
    int bx = blockIdx.x, tid = threadIdx.x;
    if (bx < PB_Z) {
        int i = bx * 256 + tid;
        if (i < NN) g_deg[i] = 0;
        if (i < NCELL) g_bcnt[i] = 0;
        if (bx == 0 && tid < 32) {
            int nz = (e[2 * tid + 1] != 0) ? 1 : 0;
            unsigned m = __ballot_sync(0xffffffffu, nz);
            if (tid == 0) { g_e64 = (m == 0u) ? 1 : 0; g_maxdeg = 0; }
        }
    } else if (bx < PB_W1) {
        int n = bx - PB_Z;
        #pragma unroll
        for (int it = 0; it < 2; it++) {
            int r = it * 256 + tid;
            int col;
            if      (r < CT)   col = r + 2;
            else if (r == 484) col = 0;
            else if (r == 485) col = 1;
            else if (r == 486) col = 486;
            else if (r == 487) col = 487;
            else               col = -1;
            float v = (col >= 0) ? W1[n * KIN + col] : 0.0f;
            g_W1t[n * 512 + permpos(r)] = __uint_as_float(to_tf32(v));
        }
    } else if (bx < PB_W2) {
        int n = (bx - PB_W1) * 2 + (tid >> 7), k = tid & 127;
        float v = W2[n * HID + k];
        g_W2t[n * 128 + permpos(k)] = __uint_as_float(to_tf32(v));
    } else {
        __shared__ float t[32][33];
        int i = bx - PB_W2;
        int c0 = (i & 15) * 32, p0 = (i >> 4) * 32;
        int tx = tid & 31, ty = tid >> 5;    // 32 x 8
        #pragma unroll
        for (int q = 0; q < 4; q++) {
            int c = c0 + ty + q * 8;
            float v = 0.0f;
            if (c < CT)
                v = (c < CBB) ? bb[(size_t)c * NPIX + p0 + tx]
                              : seg[(size_t)(c - CBB) * NPIX + p0 + tx];
            t[ty + q * 8][tx] = v;
        }
        __syncthreads();
        #pragma unroll
        for (int q = 0; q < 4; q++) {
            int p = p0 + ty + q * 8;
            int c = c0 + tx;
            if (c < CT) g_ft[(size_t)p * CT + c] = t[tx][ty + q * 8];
        }
    }
}

__global__ void k_hist(const float* __restrict__ verts) {
    int i = blockIdx.x * blockDim.x + threadIdx.x;
    if (i < NN)
        atomicAdd(&g_bcnt[cell_of(verts[2 * i], verts[2 * i + 1])], 1);
}

// single-block exclusive scan of g_bcnt (16384) -> g_boff
__global__ void k_scan() {
    __shared__ int ps[1024];
    const int t = threadIdx.x;
    const int base = t * 16;
    int loc[16], sum = 0;
    #pragma unroll
    for (int j = 0; j < 16; j++) { loc[j] = sum; sum += g_bcnt[base + j]; }
    ps[t] = sum;
    __syncthreads();
    // Hillis-Steele inclusive scan over 1024 partials
    for (int o = 1; o < 1024; o <<= 1) {
        int v = (t >= o) ? ps[t - o] : 0;
        __syncthreads();
        ps[t] += v;
        __syncthreads();
    }
    int excl = ps[t] - sum;     // exclusive prefix for this thread's block of 16
    #pragma unroll
    for (int j = 0; j < 16; j++) g_boff[base + j] = excl + loc[j];
}

__global__ void k_scatter(const float* __restrict__ verts) {
    int i = blockIdx.x * blockDim.x + threadIdx.x;
    if (i < NN) {
        int c = cell_of(verts[2 * i], verts[2 * i + 1]);
        int pos = atomicAdd(&g_boff[c], 1);
        g_perm[pos] = i;
    }
}

__global__ void k_degree(const void* __restrict__ eptr) {
    const int total = 2 * NEDGE;
    const bool is64 = (g_e64 != 0);
    const long long* __restrict__ e64 = (const long long*)eptr;
    const int* __restrict__ e32 = (const int*)eptr;
    for (int i = blockIdx.x * blockDim.x + threadIdx.x; i < total; i += gridDim.x * blockDim.x) {
        int idx = is64 ? (int)e64[i] : e32[i];
        atomicAdd(&g_deg[idx], 1);
    }
}

__global__ void k_max() {
    int i = blockIdx.x * blockDim.x + threadIdx.x;
    int v = (i < NN) ? g_deg[i] : 0;
    #pragma unroll
    for (int o = 16; o > 0; o >>= 1) v = max(v, __shfl_down_sync(0xffffffffu, v, o));
    if ((threadIdx.x & 31) == 0) atomicMax(&g_maxdeg, v);
}

// ---------------- main: cell-sorted gather + tf32 mma.sync ----------------
__global__ void __launch_bounds__(256, 2) k_main(
    const float* __restrict__ verts,
    const float* __restrict__ b1,
    const float* __restrict__ b2,
    float* __restrict__ out)
{
    extern __shared__ char smem[];
    int4*   Pq = (int4*)(smem + PQ_OFF);
    float4* Wq = (float4*)(smem + WQ_OFF);
    float4* Sq = (float4*)(smem + SQ_OFF);
    int*    Nd = (int*)(smem + ND_OFF);

    const int tid = threadIdx.x;
    const int m0 = blockIdx.x * 128;

    // per-node params (nodes in cell-sorted order)
    if (tid < 128) {
        int node = g_perm[min(m0 + tid, NN - 1)];
        Nd[tid] = node;
        float vx = verts[2 * node], vy = verts[2 * node + 1];
        float ix = vx * (127.0f / 512.0f), iy = vy * (127.0f / 512.0f);
        float fx = floorf(ix), fy = floorf(iy);
        float wx = ix - fx, wy = iy - fy;
        int x0 = min(max((int)fx, 0), FDIM - 1);
        int x1 = min(x0 + 1, FDIM - 1);
        int y0 = min(max((int)fy, 0), FDIM - 1);
        int y1 = min(y0 + 1, FDIM - 1);
        Pq[tid] = make_int4((y0 * FDIM + x0) * CT, (y0 * FDIM + x1) * CT,
                            (y1 * FDIM + x0) * CT, (y1 * FDIM + x1) * CT);
        Wq[tid] = make_float4((1.0f - wx) * (1.0f - wy), wx * (1.0f - wy),
                              (1.0f - wx) * wy, wx * wy);
        float dg = (float)g_deg[node] / ((float)g_maxdeg + 1e-6f);
        float dx = fminf(vx, 512.0f - vx), dy = fminf(vy, 512.0f - vy);
        Sq[tid] = make_float4(vx * (1.0f / 512.0f), vy * (1.0f / 512.0f),
                              dg, fminf(dx, dy) * (1.0f / 256.0f));
    }
    __syncthreads();

    const int warp = tid >> 5, lane = tid & 31;
    const int g  = lane >> 2, tr = lane & 3, tc = tr * 2;
    const int wM = (warp & 3) * 32, wN = (warp >> 2) * 64;
    const int kq = tid & 7;               // builder k-quad
    const int ms = tid >> 3;              // builder m slot (0..31), m = ms*4 + s
    const int kofs = kq * 16;             // builder store byte offset

    float acc[2][8][4];
    #pragma unroll
    for (int a = 0; a < 2; a++)
        #pragma unroll
        for (int b = 0; b < 8; b++)
            #pragma unroll
            for (int c = 0; c < 4; c++) acc[a][b][c] = 0.0f;

    // -------- prologue: build A(0), fill B(0) --------
    b1fill(0, smem + B1_OFF(0), tid);
    CP_COMMIT();
    #pragma unroll
    for (int s = 0; s < 4; s++) {
        float4 f[4];
        int m = ms * 4 + s;
        bld_issue4(Pq, m, kq * 4, f);
        bld_store4(Wq, Sq, m, kq * 4, f, smem + A1_OFF(0) + m * A1_STR + kofs);
    }
    CP_WAIT0();
    __syncthreads();

    // ================= GEMM1: 16 chunks of 32 =================
    #pragma unroll 1
    for (int c = 0; c < 16; c++) {
        const char* A = smem + A1_OFF(c & 1);
        const char* B = smem + B1_OFF(c & 1);
        char* nA = smem + A1_OFF((c + 1) & 1);
        const bool more = (c < 15);

        if (more) b1fill(c + 1, smem + B1_OFF((c + 1) & 1), tid);
        else      b2fill(0, smem + B2_OFF, tid);        // prefetch W2 chunk 0
        CP_COMMIT();

        const int k0n = (c + 1) * 32 + kq * 4;
        #pragma unroll
        for (int s = 0; s < 4; s++) {                   // k8 segments; builder batch = s
            float4 f[4];
            const int mB = ms * 4 + s;
            if (more) bld_issue4(Pq, mB, k0n, f);

            uint32_t a0[4], a1[4];
            ldA(a0, A, wM + g,      s * 8 + tr, A1_STR);
            ldA(a1, A, wM + 16 + g, s * 8 + tr, A1_STR);
            #pragma unroll
            for (int nb = 0; nb < 8; nb++) {
                uint2 bfr = *(const uint2*)(B + (wN + nb * 8 + g) * B1_STR + s * 32 + tr * 8);
                mma_tf32(acc[0][nb], a0, bfr.x, bfr.y);
                mma_tf32(acc[1][nb], a1, bfr.x, bfr.y);
            }
            if (more) bld_store4(Wq, Sq, mB, k0n, f, nA + mB * A1_STR + kofs);
        }
        CP_WAIT0();
        __syncthreads();
    }

    // -------- epilogue 1: h1 = relu(D1 + b1) -> tf32 smem tile A2 --------
    {
        char* A2 = smem + A2_OFF;
        #pragma unroll
        for (int mb = 0; mb < 2; mb++) {
            int row = wM + mb * 16 + g;
            #pragma unroll
            for (int nb = 0; nb < 8; nb++) {
                int col = wN + nb * 8 + tc;
                float2 bb = *(const float2*)(b1 + col);
                float v0 = fmaxf(acc[mb][nb][0] + bb.x, 0.0f);
                float v1 = fmaxf(acc[mb][nb][1] + bb.y, 0.0f);
                float v2 = fmaxf(acc[mb][nb][2] + bb.x, 0.0f);
                float v3 = fmaxf(acc[mb][nb][3] + bb.y, 0.0f);
                *(uint2*)(A2 + row * A2_STR + col * 4)       = make_uint2(to_tf32(v0), to_tf32(v1));
                *(uint2*)(A2 + (row + 8) * A2_STR + col * 4) = make_uint2(to_tf32(v2), to_tf32(v3));
            }
        }
    }
    #pragma unroll
    for (int a = 0; a < 2; a++)
        #pragma unroll
        for (int b = 0; b < 8; b++)
            #pragma unroll
            for (int c = 0; c < 4; c++) acc[a][b][c] = 0.0f;
    __syncthreads();

    // ================= GEMM2: 4 chunks of 32 (single B2 buffer, prefetched) =================
    #pragma unroll 1
    for (int c2 = 0; c2 < 4; c2++) {
        const char* A2 = smem + A2_OFF;
        const char* B = smem + B2_OFF;
        #pragma unroll
        for (int s = 0; s < 4; s++) {
            uint32_t a0[4], a1[4];
            int col = c2 * 32 + s * 8 + tr;
            ldA(a0, A2, wM + g,      col, A2_STR);
            ldA(a1, A2, wM + 16 + g, col, A2_STR);
            #pragma unroll
            for (int nb = 0; nb < 8; nb++) {
                uint2 bfr = *(const uint2*)(B + (wN + nb * 8 + g) * B2_STR + s * 32 + tr * 8);
                mma_tf32(acc[0][nb], a0, bfr.x, bfr.y);
                mma_tf32(acc[1][nb], a1, bfr.x, bfr.y);
            }
        }
        if (c2 < 3) {
            __syncthreads();                 // all reads of B2 done
            b2fill(c2 + 1, smem + B2_OFF, tid);
            CP_COMMIT(); CP_WAIT0();
            __syncthreads();
        }
    }

    // -------- epilogue 2: out = relu(D2 + b2), scatter to original node rows --------
    #pragma unroll
    for (int mb = 0; mb < 2; mb++) {
        int r1 = wM + mb * 16 + g;
        int n1 = Nd[r1], n2 = Nd[r1 + 8];
        #pragma unroll
        for (int nb = 0; nb < 8; nb++) {
            int col = wN + nb * 8 + tc;
            float2 bb = *(const float2*)(b2 + col);
            float2 v1 = make_float2(fmaxf(acc[mb][nb][0] + bb.x, 0.0f),
                                    fmaxf(acc[mb][nb][1] + bb.y, 0.0f));
            float2 v2 = make_float2(fmaxf(acc[mb][nb][2] + bb.x, 0.0f),
                                    fmaxf(acc[mb][nb][3] + bb.y, 0.0f));
            *(float2*)(out + (size_t)n1 * HID + col) = v1;
            *(float2*)(out + (size_t)n2 * HID + col) = v2;
        }
    }
}

// ---------------- launch ----------------
extern "C" void kernel_launch(void* const* d_in, const int* in_sizes, int n_in,
                              void* d_out, int out_size)
{
    const float* verts = (const float*)d_in[0];
    const float* bb    = (const float*)d_in[1];
    const float* seg   = (const float*)d_in[2];
    const void*  edges = d_in[3];
    const float* W1    = (const float*)d_in[4];
    const float* b1    = (const float*)d_in[5];
    const float* W2    = (const float*)d_in[6];
    const float* b2    = (const float*)d_in[7];
    float* out = (float*)d_out;

    k_prep<<<PB_T, 256>>>((const int*)edges, W1, W2, bb, seg);
    k_hist<<<(NN + 255) / 256, 256>>>(verts);
    k_scan<<<1, 1024>>>();
    k_scatter<<<(NN + 255) / 256, 256>>>(verts);
    k_degree<<<2048, 256>>>(edges);
    k_max<<<(NN + 255) / 256, 256>>>();

    cudaFuncSetAttribute(k_main, cudaFuncAttributeMaxDynamicSharedMemorySize, SMEM_BYTES);
    k_main<<<(NN + 127) / 128, 256, SMEM_BYTES>>>(verts, b1, b2, out);
}

// round 16
// speedup vs baseline: 2.0002x; 2.0002x over previous
#include <cuda_runtime.h>
#include <math.h>
#include <stdint.h>

// ---------------- problem constants ----------------
#define NN     200000
#define NEDGE  800000
#define CBB    480
#define CT     484
#define FDIM   128
#define NPIX   (FDIM*FDIM)
#define HID    128
#define KIN    488
#define NCELL  (FDIM*FDIM)

// ---------------- k_Y smem (bytes) ----------------
#define A1_STR   144
#define B1_STR   160
#define A1_OFF(b) ((b)*18432)          // 2 x 128x144
#define B1_OFF(b) (36864 + (b)*20480)  // 2 x 128x160
#define KY_SMEM  77824

// ---------------- k_main smem (bytes) ----------------
#define A2_OFF   0
#define A2_STR   528                   // 132 floats
#define B2_OFF   67584                 // 128 x 160
#define B2_STR   160
#define PQ_OFF   88064                 // int4[128]  (byte offsets into g_Y)
#define WQ_OFF   90112                 // float4[128] bilinear weights
#define SQ_OFF   92160                 // float4[128] scalar feats
#define ND_OFF   94208                 // int[128] node ids
#define SW_OFF   94720                 // 4 x 128 floats (W1 scalar cols)
#define SB_OFF   96768                 // 128 floats (b1)
#define KM_SMEM  97280                 // x2 CTAs = 194560

// ---------------- device scratch ----------------
__device__ float g_ftp[(size_t)NPIX * 512];     // (pixel, 512) tf32-rounded, zero-padded (33.5MB)
__device__ float g_Y[(size_t)NPIX * HID];       // Y = ft @ W1^T per pixel (8.4MB)
__device__ float g_W1t[128*512];                // [n][k'] tf32, permuted cols + pair-permute
__device__ float g_W2t[128*128];                // [n][k] tf32, pair-permute
__device__ float g_W1s[4*128];                  // W1 cols {0,1,486,487} raw fp32
__device__ int g_deg[NN];
__device__ int g_perm[NN];
__device__ int g_bcnt[NCELL];
__device__ int g_boff[NCELL];
__device__ int g_maxdeg;
__device__ int g_e64;

// pair-permute within each 8: col j -> 2*(j%4) + j/4
__device__ __forceinline__ int permpos(int r) {
    return (r & ~7) + ((r & 3) << 1) + ((r >> 2) & 1);
}

// ---------------- helpers ----------------
__device__ __forceinline__ void cp16(void* s, const void* g) {
    unsigned ss = (unsigned)__cvta_generic_to_shared(s);
    asm volatile("cp.async.cg.shared.global [%0], [%1], 16;" :: "r"(ss), "l"(g));
}
#define CP_COMMIT() asm volatile("cp.async.commit_group;")
#define CP_WAIT0()  asm volatile("cp.async.wait_group 0;" ::: "memory")

__device__ __forceinline__ uint32_t to_tf32(float v) {
    uint32_t r;
    asm("cvt.rna.tf32.f32 %0, %1;" : "=r"(r) : "f"(v));
    return r;
}
__device__ __forceinline__ void mma_tf32(float* d, const uint32_t* a, uint32_t b0, uint32_t b1) {
    asm("mma.sync.aligned.m16n8k8.row.col.f32.tf32.tf32.f32 "
        "{%0,%1,%2,%3}, {%4,%5,%6,%7}, {%8,%9}, {%0,%1,%2,%3};"
        : "+f"(d[0]), "+f"(d[1]), "+f"(d[2]), "+f"(d[3])
        : "r"(a[0]), "r"(a[1]), "r"(a[2]), "r"(a[3]), "r"(b0), "r"(b1));
}
__device__ __forceinline__ void ldA(uint32_t* a, const char* A, int row, int col, int str) {
    const char* p = A + row * str + col * 4;
    a[0] = *(const uint32_t*)p;
    a[1] = *(const uint32_t*)(p + 8 * str);
    a[2] = *(const uint32_t*)(p + 16);
    a[3] = *(const uint32_t*)(p + 8 * str + 16);
}

__device__ __forceinline__ void a1fill(int p0, int c, char* dst, int tid) {
    #pragma unroll
    for (int i = 0; i < 4; i++) {
        int id = tid * 4 + i;            // 1024 granules of 16B
        int r = id >> 3, g8 = id & 7;
        cp16(dst + r * A1_STR + g8 * 16,
             (const char*)g_ftp + (size_t)(p0 + r) * 2048 + c * 128 + g8 * 16);
    }
}
__device__ __forceinline__ void b1fill(int c, char* dst, int tid) {
    #pragma unroll
    for (int i = 0; i < 4; i++) {
        int id = tid * 4 + i;
        int r = id >> 3, g8 = id & 7;
        cp16(dst + r * B1_STR + g8 * 16, (const char*)g_W1t + r * 2048 + c * 128 + g8 * 16);
    }
}
__device__ __forceinline__ void b2fill(int c, char* dst, int tid) {
    #pragma unroll
    for (int i = 0; i < 4; i++) {
        int id = tid * 4 + i;
        int r = id >> 3, g8 = id & 7;
        cp16(dst + r * B2_STR + g8 * 16, (const char*)g_W2t + r * 512 + c * 128 + g8 * 16);
    }
}

__device__ __forceinline__ int cell_of(float vx, float vy) {
    int x0 = min(max((int)floorf(vx * (127.0f / 512.0f)), 0), FDIM - 1);
    int y0 = min(max((int)floorf(vy * (127.0f / 512.0f)), 0), FDIM - 1);
    return y0 * FDIM + x0;
}

// ---------------- prep kernels ----------------
#define PB_Z   782
#define PB_W1  (PB_Z + 128)
#define PB_W2  (PB_W1 + 64)
#define PB_WS  (PB_W2 + 1)
#define PB_T   (PB_WS + 8192)

__global__ void k_prep(const int* __restrict__ e,
                       const float* __restrict__ W1, const float* __restrict__ W2,
                       const float* __restrict__ bb, const float* __restrict__ seg) {
    int bx = blockIdx.x, tid = threadIdx.x;
    if (bx < PB_Z) {
        int i = bx * 256 + tid;
        if (i < NN) g_deg[i] = 0;
        if (i < NCELL) g_bcnt[i] = 0;
        if (bx == 0 && tid < 32) {
            int nz = (e[2 * tid + 1] != 0) ? 1 : 0;
            unsigned m = __ballot_sync(0xffffffffu, nz);
            if (tid == 0) { g_e64 = (m == 0u) ? 1 : 0; g_maxdeg = 0; }
        }
    } else if (bx < PB_W1) {
        int n = bx - PB_Z;
        #pragma unroll
        for (int it = 0; it < 2; it++) {
            int r = it * 256 + tid;
            int col;
            if      (r < CT)   col = r + 2;
            else if (r == 484) col = 0;
            else if (r == 485) col = 1;
            else if (r == 486) col = 486;
            else if (r == 487) col = 487;
            else               col = -1;
            float v = (col >= 0) ? W1[n * KIN + col] : 0.0f;
            g_W1t[n * 512 + permpos(r)] = __uint_as_float(to_tf32(v));
        }
    } else if (bx < PB_W2) {
        int n = (bx - PB_W1) * 2 + (tid >> 7), k = tid & 127;
        float v = W2[n * HID + k];
        g_W2t[n * 128 + permpos(k)] = __uint_as_float(to_tf32(v));
    } else if (bx < PB_WS) {
        // W1 scalar cols {0,1,486,487}, raw fp32; 512 entries, 256 threads x2
        #pragma unroll
        for (int it = 0; it < 2; it++) {
            int i = it * 256 + tid;
            int cI = i >> 7, n = i & 127;
            int col = (cI == 0) ? 0 : (cI == 1) ? 1 : (cI == 2) ? 486 : 487;
            g_W1s[cI * 128 + n] = W1[n * KIN + col];
        }
    } else {
        __shared__ float t[32][33];
        int i = bx - PB_WS;
        int c0 = (i & 15) * 32, p0 = (i >> 4) * 32;
        int tx = tid & 31, ty = tid >> 5;    // 32 x 8
        #pragma unroll
        for (int q = 0; q < 4; q++) {
            int c = c0 + ty + q * 8;
            float v = 0.0f;
            if (c < CT)
                v = (c < CBB) ? bb[(size_t)c * NPIX + p0 + tx]
                              : seg[(size_t)(c - CBB) * NPIX + p0 + tx];
            t[ty + q * 8][tx] = v;
        }
        __syncthreads();
        #pragma unroll
        for (int q = 0; q < 4; q++) {
            int p = p0 + ty + q * 8;
            int c = c0 + tx;
            g_ftp[(size_t)p * 512 + c] = __uint_as_float(to_tf32(t[tx][ty + q * 8]));
        }
    }
}

__global__ void k_hist(const float* __restrict__ verts) {
    int i = blockIdx.x * blockDim.x + threadIdx.x;
    if (i < NN)
        atomicAdd(&g_bcnt[cell_of(verts[2 * i], verts[2 * i + 1])], 1);
}

__global__ void k_scan() {
    __shared__ int ps[1024];
    const int t = threadIdx.x;
    const int base = t * 16;
    int loc[16], sum = 0;
    #pragma unroll
    for (int j = 0; j < 16; j++) { loc[j] = sum; sum += g_bcnt[base + j]; }
    ps[t] = sum;
    __syncthreads();
    for (int o = 1; o < 1024; o <<= 1) {
        int v = (t >= o) ? ps[t - o] : 0;
        __syncthreads();
        ps[t] += v;
        __syncthreads();
    }
    int excl = ps[t] - sum;
    #pragma unroll
    for (int j = 0; j < 16; j++) g_boff[base + j] = excl + loc[j];
}

__global__ void k_scatter(const float* __restrict__ verts) {
    int i = blockIdx.x * blockDim.x + threadIdx.x;
    if (i < NN) {
        int c = cell_of(verts[2 * i], verts[2 * i + 1]);
        int pos = atomicAdd(&g_boff[c], 1);
        g_perm[pos] = i;
    }
}

__global__ void k_degree(const void* __restrict__ eptr) {
    const int total = 2 * NEDGE;
    const bool is64 = (g_e64 != 0);
    const long long* __restrict__ e64 = (const long long*)eptr;
    const int* __restrict__ e32 = (const int*)eptr;
    for (int i = blockIdx.x * blockDim.x + threadIdx.x; i < total; i += gridDim.x * blockDim.x) {
        int idx = is64 ? (int)e64[i] : e32[i];
        atomicAdd(&g_deg[idx], 1);
    }
}

__global__ void k_max() {
    int i = blockIdx.x * blockDim.x + threadIdx.x;
    int v = (i < NN) ? g_deg[i] : 0;
    #pragma unroll
    for (int o = 16; o > 0; o >>= 1) v = max(v, __shfl_down_sync(0xffffffffu, v, o));
    if ((threadIdx.x & 31) == 0) atomicMax(&g_maxdeg, v);
}

// ---------------- k_Y: Y[p] = W1 @ ft[p] for all 16384 pixels ----------------
__global__ void __launch_bounds__(256, 2) k_Y() {
    extern __shared__ char smem[];
    const int tid = threadIdx.x;
    const int p0 = blockIdx.x * 128;
    const int warp = tid >> 5, lane = tid & 31;
    const int g  = lane >> 2, tr = lane & 3, tc = tr * 2;
    const int wM = (warp & 3) * 32, wN = (warp >> 2) * 64;

    float acc[2][8][4];
    #pragma unroll
    for (int a = 0; a < 2; a++)
        #pragma unroll
        for (int b = 0; b < 8; b++)
            #pragma unroll
            for (int c = 0; c < 4; c++) acc[a][b][c] = 0.0f;

    a1fill(p0, 0, smem + A1_OFF(0), tid);
    b1fill(0, smem + B1_OFF(0), tid);
    CP_COMMIT(); CP_WAIT0();
    __syncthreads();

    #pragma unroll 1
    for (int c = 0; c < 16; c++) {
        const char* A = smem + A1_OFF(c & 1);
        const char* B = smem + B1_OFF(c & 1);
        if (c < 15) {
            a1fill(p0, c + 1, smem + A1_OFF((c + 1) & 1), tid);
            b1fill(c + 1, smem + B1_OFF((c + 1) & 1), tid);
        }
        CP_COMMIT();
        #pragma unroll
        for (int s = 0; s < 4; s++) {
            uint32_t a0[4], a1[4];
            ldA(a0, A, wM + g,      s * 8 + tr, A1_STR);
            ldA(a1, A, wM + 16 + g, s * 8 + tr, A1_STR);
            #pragma unroll
            for (int nb = 0; nb < 8; nb++) {
                uint2 bfr = *(const uint2*)(B + (wN + nb * 8 + g) * B1_STR + s * 32 + tr * 8);
                mma_tf32(acc[0][nb], a0, bfr.x, bfr.y);
                mma_tf32(acc[1][nb], a1, bfr.x, bfr.y);
            }
        }
        CP_WAIT0();
        __syncthreads();
    }

    // write Y (raw, no bias/relu)
    #pragma unroll
    for (int mb = 0; mb < 2; mb++) {
        int r1 = p0 + wM + mb * 16 + g;
        #pragma unroll
        for (int nb = 0; nb < 8; nb++) {
            int col = wN + nb * 8 + tc;
            *(float2*)(g_Y + (size_t)r1 * HID + col)       = make_float2(acc[mb][nb][0], acc[mb][nb][1]);
            *(float2*)(g_Y + (size_t)(r1 + 8) * HID + col) = make_float2(acc[mb][nb][2], acc[mb][nb][3]);
        }
    }
}

// ---------------- k_main: combine Y + scalars -> h1, then GEMM2 ----------------
__global__ void __launch_bounds__(256, 2) k_main(
    const float* __restrict__ verts,
    const float* __restrict__ b1,
    const float* __restrict__ b2,
    float* __restrict__ out)
{
    extern __shared__ char smem[];
    int4*   Pq = (int4*)(smem + PQ_OFF);
    float4* Wq = (float4*)(smem + WQ_OFF);
    float4* Sq = (float4*)(smem + SQ_OFF);
    int*    Nd = (int*)(smem + ND_OFF);

    const int tid = threadIdx.x;
    const int m0 = blockIdx.x * 128;

    // prefetch B2 chunk 0 during combine
    b2fill(0, smem + B2_OFF, tid);
    CP_COMMIT();

    // W1 scalar cols + b1 into smem
    {
        float* sw = (float*)(smem + SW_OFF);
        sw[tid] = g_W1s[tid];
        sw[tid + 256] = g_W1s[tid + 256];
        if (tid < 128) ((float*)(smem + SB_OFF))[tid] = b1[tid];
    }

    // per-node params (cell-sorted order)
    if (tid < 128) {
        int node = g_perm[min(m0 + tid, NN - 1)];
        Nd[tid] = node;
        float vx = verts[2 * node], vy = verts[2 * node + 1];
        float ix = vx * (127.0f / 512.0f), iy = vy * (127.0f / 512.0f);
        float fx = floorf(ix), fy = floorf(iy);
        float wx = ix - fx, wy = iy - fy;
        int x0 = min(max((int)fx, 0), FDIM - 1);
        int x1 = min(x0 + 1, FDIM - 1);
        int y0 = min(max((int)fy, 0), FDIM - 1);
        int y1 = min(y0 + 1, FDIM - 1);
        Pq[tid] = make_int4((y0 * FDIM + x0) * 512, (y0 * FDIM + x1) * 512,
                            (y1 * FDIM + x0) * 512, (y1 * FDIM + x1) * 512);   // byte offsets into g_Y
        Wq[tid] = make_float4((1.0f - wx) * (1.0f - wy), wx * (1.0f - wy),
                              (1.0f - wx) * wy, wx * wy);
        float dg = (float)g_deg[node] / ((float)g_maxdeg + 1e-6f);
        float dx = fminf(vx, 512.0f - vx), dy = fminf(vy, 512.0f - vy);
        Sq[tid] = make_float4(vx * (1.0f / 512.0f), vy * (1.0f / 512.0f),
                              dg, fminf(dx, dy) * (1.0f / 256.0f));
    }
    __syncthreads();

    // -------- combine: h1 = relu(sum wi*Y[qi] + s*W1s + b1) -> A2 (tf32) --------
    {
        const int m = tid >> 1, h = tid & 1;
        int4 q = Pq[m];
        float4 w = Wq[m];
        float4 s = Sq[m];
        const char* Yb = (const char*)g_Y;
        const float4* y0 = (const float4*)(Yb + q.x + h * 256);
        const float4* y1 = (const float4*)(Yb + q.y + h * 256);
        const float4* y2 = (const float4*)(Yb + q.z + h * 256);
        const float4* y3 = (const float4*)(Yb + q.w + h * 256);
        const float4* c0 = (const float4*)(smem + SW_OFF + 0 * 512 + h * 256);
        const float4* c1 = (const float4*)(smem + SW_OFF + 1 * 512 + h * 256);
        const float4* c2 = (const float4*)(smem + SW_OFF + 2 * 512 + h * 256);
        const float4* c3 = (const float4*)(smem + SW_OFF + 3 * 512 + h * 256);
        const float4* sb = (const float4*)(smem + SB_OFF + h * 256);
        char* dst = smem + A2_OFF + m * A2_STR + h * 256;
        #pragma unroll
        for (int j = 0; j < 16; j++) {
            float4 a = sb[j];
            float4 v0 = y0[j], v1 = y1[j], v2 = y2[j], v3 = y3[j];
            float4 d0 = c0[j], d1 = c1[j], d2 = c2[j], d3 = c3[j];
            a.x += w.x * v0.x + w.y * v1.x + w.z * v2.x + w.w * v3.x
                 + s.x * d0.x + s.y * d1.x + s.z * d2.x + s.w * d3.x;
            a.y += w.x * v0.y + w.y * v1.y + w.z * v2.y + w.w * v3.y
                 + s.x * d0.y + s.y * d1.y + s.z * d2.y + s.w * d3.y;
            a.z += w.x * v0.z + w.y * v1.z + w.z * v2.z + w.w * v3.z
                 + s.x * d0.z + s.y * d1.z + s.z * d2.z + s.w * d3.z;
            a.w += w.x * v0.w + w.y * v1.w + w.z * v2.w + w.w * v3.w
                 + s.x * d0.w + s.y * d1.w + s.z * d2.w + s.w * d3.w;
            uint4 t = make_uint4(to_tf32(fmaxf(a.x, 0.0f)), to_tf32(fmaxf(a.y, 0.0f)),
                                 to_tf32(fmaxf(a.z, 0.0f)), to_tf32(fmaxf(a.w, 0.0f)));
            *(uint4*)(dst + j * 16) = t;
        }
    }
    CP_WAIT0();
    __syncthreads();

    // -------- GEMM2: out = relu(h1 @ W2^T + b2) --------
    const int warp = tid >> 5, lane = tid & 31;
    const int g  = lane >> 2, tr = lane & 3, tc = tr * 2;
    const int wM = (warp & 3) * 32, wN = (warp >> 2) * 64;

    float acc[2][8][4];
    #pragma unroll
    for (int a = 0; a < 2; a++)
        #pragma unroll
        for (int b = 0; b < 8; b++)
            #pragma unroll
            for (int c = 0; c < 4; c++) acc[a][b][c] = 0.0f;

    #pragma unroll 1
    for (int c2 = 0; c2 < 4; c2++) {
        const char* A2 = smem + A2_OFF;
        const char* B = smem + B2_OFF;
        #pragma unroll
        for (int s = 0; s < 4; s++) {
            uint32_t a0[4], a1[4];
            int col = c2 * 32 + s * 8 + tr;
            ldA(a0, A2, wM + g,      col, A2_STR);
            ldA(a1, A2, wM + 16 + g, col, A2_STR);
            #pragma unroll
            for (int nb = 0; nb < 8; nb++) {
                uint2 bfr = *(const uint2*)(B + (wN + nb * 8 + g) * B2_STR + s * 32 + tr * 8);
                mma_tf32(acc[0][nb], a0, bfr.x, bfr.y);
                mma_tf32(acc[1][nb], a1, bfr.x, bfr.y);
            }
        }
        if (c2 < 3) {
            __syncthreads();
            b2fill(c2 + 1, smem + B2_OFF, tid);
            CP_COMMIT(); CP_WAIT0();
            __syncthreads();
        }
    }

    // epilogue: out = relu(D2 + b2), scatter to original node rows
    #pragma unroll
    for (int mb = 0; mb < 2; mb++) {
        int r1 = wM + mb * 16 + g;
        int n1 = Nd[r1], n2 = Nd[r1 + 8];
        #pragma unroll
        for (int nb = 0; nb < 8; nb++) {
            int col = wN + nb * 8 + tc;
            float2 bb = *(const float2*)(b2 + col);
            float2 v1 = make_float2(fmaxf(acc[mb][nb][0] + bb.x, 0.0f),
                                    fmaxf(acc[mb][nb][1] + bb.y, 0.0f));
            float2 v2 = make_float2(fmaxf(acc[mb][nb][2] + bb.x, 0.0f),
                                    fmaxf(acc[mb][nb][3] + bb.y, 0.0f));
            *(float2*)(out + (size_t)n1 * HID + col) = v1;
            *(float2*)(out + (size_t)n2 * HID + col) = v2;
        }
    }
}

// ---------------- launch ----------------
extern "C" void kernel_launch(void* const* d_in, const int* in_sizes, int n_in,
                              void* d_out, int out_size)
{
    const float* verts = (const float*)d_in[0];
    const float* bb    = (const float*)d_in[1];
    const float* seg   = (const float*)d_in[2];
    const void*  edges = d_in[3];
    const float* W1    = (const float*)d_in[4];
    const float* b1    = (const float*)d_in[5];
    const float* W2    = (const float*)d_in[6];
    const float* b2    = (const float*)d_in[7];
    float* out = (float*)d_out;

    k_prep<<<PB_T, 256>>>((const int*)edges, W1, W2, bb, seg);
    k_hist<<<(NN + 255) / 256, 256>>>(verts);
    k_scan<<<1, 1024>>>();
    k_scatter<<<(NN + 255) / 256, 256>>>(verts);
    k_degree<<<2048, 256>>>(edges);
    k_max<<<(NN + 255) / 256, 256>>>();

    cudaFuncSetAttribute(k_Y, cudaFuncAttributeMaxDynamicSharedMemorySize, KY_SMEM);
    k_Y<<<NPIX / 128, 256, KY_SMEM>>>();

    cudaFuncSetAttribute(k_main, cudaFuncAttributeMaxDynamicSharedMemorySize, KM_SMEM);
    k_main<<<(NN + 127) / 128, 256, KM_SMEM>>>(verts, b1, b2, out);
}